// round 7
// baseline (speedup 1.0000x reference)
#include <cuda_runtime.h>

#define DD 512
#define BB 128
#define EPSF 1e-5f
#define LOG2E_F 1.4426950408889634f
#define TJ 32

// scratch (static device memory — no allocations)
__device__ float g_wk[3 * BB * DD];
__device__ float g_wq[3 * BB * DD];
__device__ float g_y [3 * BB * DD];
__device__ float g_wt[3 * DD * DD];     // k-major weights: [mat][k][m]

struct Ptr3 { const float* p[3]; };

__device__ __forceinline__ float ex2f(float x) {
    float y;
    asm("ex2.approx.ftz.f32 %0, %1;" : "=f"(y) : "f"(x));
    return y;
}

__device__ __forceinline__ void split_tf32(float a, unsigned& hi, unsigned& lo) {
    asm("cvt.rna.tf32.f32 %0, %1;" : "=r"(hi) : "f"(a));
    float r = a - __uint_as_float(hi);
    asm("cvt.rna.tf32.f32 %0, %1;" : "=r"(lo) : "f"(r));
}

#define MMA_TF32(d, a0, a1, a2, a3, b0, b1)                                   \
    asm volatile(                                                             \
        "mma.sync.aligned.m16n8k8.row.col.f32.tf32.tf32.f32 "                 \
        "{%0,%1,%2,%3}, {%4,%5,%6,%7}, {%8,%9}, {%0,%1,%2,%3};"               \
        : "+f"(d[0]), "+f"(d[1]), "+f"(d[2]), "+f"(d[3])                      \
        : "r"(a0), "r"(a1), "r"(a2), "r"(a3), "r"(b0), "r"(b1))

// ===================== transpose weights: g_wt[z][d][m] = W_z[m][d] =====================
__global__ void __launch_bounds__(256)
k_transpose(const float* __restrict__ W0, const float* __restrict__ W1,
            const float* __restrict__ W2)
{
    __shared__ float t[32][33];
    const float* W = (blockIdx.z == 0) ? W0 : (blockIdx.z == 1) ? W1 : W2;
    float* O = g_wt + (size_t)blockIdx.z * DD * DD;
    int x  = blockIdx.x * 32 + threadIdx.x;
    int y0 = blockIdx.y * 32;
    #pragma unroll
    for (int i = threadIdx.y; i < 32; i += 8)
        t[i][threadIdx.x] = W[(size_t)(y0 + i) * DD + x];
    __syncthreads();
    int xo  = blockIdx.y * 32 + threadIdx.x;
    int yo0 = blockIdx.x * 32;
    #pragma unroll
    for (int i = threadIdx.y; i < 32; i += 8)
        O[(size_t)(yo0 + i) * DD + xo] = t[threadIdx.x][i];
}

// ===================== GEMM v7: tf32 tensor-core, 3x-split =====================
// out[row, m] = sum_d src[row, d] * Wt[d, m] + bias[m] (+ residual src[row, m])
// block = 128 thr (4 warps); tile = 32 rows x 64 cols; K chunked x64 via smem.
// warp w: rows (w&1)*16, cols (w>>1)*32 (4 n8-tiles).
struct G7 {
    Ptr3 src[2];
    const float* wt[2];      // k-major [512][512]
    const float* bias[2];
    float* out[2];
};

#define ASTR 68
#define WSTR 72
#define G7_SMEM ((2 * 32 * ASTR + 2 * 64 * WSTR) * 4)   // 54272 B

template <bool RES>
__global__ void __launch_bounds__(128)
k_gemm7(G7 a)
{
    extern __shared__ unsigned usm[];
    unsigned (*sA_hi)[ASTR] = (unsigned (*)[ASTR])usm;
    unsigned (*sA_lo)[ASTR] = (unsigned (*)[ASTR])(usm + 32 * ASTR);
    unsigned (*sW_hi)[WSTR] = (unsigned (*)[WSTR])(usm + 2 * 32 * ASTR);
    unsigned (*sW_lo)[WSTR] = (unsigned (*)[WSTR])(usm + 2 * 32 * ASTR + 64 * WSTR);

    int tid = threadIdx.x;
    int rt = blockIdx.x, ct = blockIdx.y, z = blockIdx.z;
    int r0 = rt * 32, c0 = ct * 64;
    int chan = r0 >> 7;
    const float* src = a.src[z].p[chan] + (size_t)(r0 & 127) * DD;
    const float* wt  = a.wt[z] + c0;

    int lane = tid & 31, w = tid >> 5;
    int gid = lane >> 2, tig = lane & 3;
    int wr = (w & 1) * 16;
    int wc = (w >> 1) * 32;

    float d[4][4];
    #pragma unroll
    for (int j = 0; j < 4; j++)
        #pragma unroll
        for (int i = 0; i < 4; i++) d[j][i] = 0.0f;

    #pragma unroll 1
    for (int ch = 0; ch < 8; ch++) {
        int kb = ch * 64;
        // stage A chunk: 32 rows x 64 k
        #pragma unroll
        for (int i = 0; i < 4; i++) {
            int idx = i * 128 + tid;
            int rr = idx >> 4, qq = (idx & 15) * 4;
            float4 v = *(const float4*)(src + (size_t)rr * DD + kb + qq);
            uint4 h, l;
            split_tf32(v.x, h.x, l.x);
            split_tf32(v.y, h.y, l.y);
            split_tf32(v.z, h.z, l.z);
            split_tf32(v.w, h.w, l.w);
            *(uint4*)&sA_hi[rr][qq] = h;
            *(uint4*)&sA_lo[rr][qq] = l;
        }
        // stage W chunk: 64 k x 64 n (wt is k-major)
        #pragma unroll
        for (int i = 0; i < 8; i++) {
            int idx = i * 128 + tid;
            int kk = idx >> 4, qq = (idx & 15) * 4;
            float4 v = *(const float4*)(wt + (size_t)(kb + kk) * DD + qq);
            uint4 h, l;
            split_tf32(v.x, h.x, l.x);
            split_tf32(v.y, h.y, l.y);
            split_tf32(v.z, h.z, l.z);
            split_tf32(v.w, h.w, l.w);
            *(uint4*)&sW_hi[kk][qq] = h;
            *(uint4*)&sW_lo[kk][qq] = l;
        }
        __syncthreads();

        #pragma unroll
        for (int ks = 0; ks < 8; ks++) {
            int k8 = ks * 8;
            unsigned ah0 = sA_hi[wr + gid    ][k8 + tig    ];
            unsigned ah1 = sA_hi[wr + gid + 8][k8 + tig    ];
            unsigned ah2 = sA_hi[wr + gid    ][k8 + tig + 4];
            unsigned ah3 = sA_hi[wr + gid + 8][k8 + tig + 4];
            unsigned al0 = sA_lo[wr + gid    ][k8 + tig    ];
            unsigned al1 = sA_lo[wr + gid + 8][k8 + tig    ];
            unsigned al2 = sA_lo[wr + gid    ][k8 + tig + 4];
            unsigned al3 = sA_lo[wr + gid + 8][k8 + tig + 4];
            #pragma unroll
            for (int j = 0; j < 4; j++) {
                int n = wc + j * 8 + gid;
                unsigned bh0 = sW_hi[k8 + tig    ][n];
                unsigned bh1 = sW_hi[k8 + tig + 4][n];
                unsigned bl0 = sW_lo[k8 + tig    ][n];
                unsigned bl1 = sW_lo[k8 + tig + 4][n];
                MMA_TF32(d[j], ah0, ah1, ah2, ah3, bh0, bh1);   // hi*hi
                MMA_TF32(d[j], ah0, ah1, ah2, ah3, bl0, bl1);   // hi*lo
                MMA_TF32(d[j], al0, al1, al2, al3, bh0, bh1);   // lo*hi
            }
        }
        __syncthreads();
    }

    // epilogue: d[j][0..1] -> (row, col..col+1), d[j][2..3] -> (row+8, ...)
    float* outp = a.out[z];
    int rowA = r0 + wr + gid;
    #pragma unroll
    for (int j = 0; j < 4; j++) {
        int col = c0 + wc + j * 8 + 2 * tig;
        float2 bb = *(const float2*)(a.bias[z] + col);
        float2 v0 = make_float2(d[j][0] + bb.x, d[j][1] + bb.y);
        float2 v1 = make_float2(d[j][2] + bb.x, d[j][3] + bb.y);
        if (RES) {
            float2 y0 = *(const float2*)(src + (size_t)(wr + gid) * DD + col);
            float2 y1 = *(const float2*)(src + (size_t)(wr + gid + 8) * DD + col);
            v0.x += y0.x; v0.y += y0.y;
            v1.x += y1.x; v1.y += y1.y;
        }
        *(float2*)(outp + (size_t)rowA * DD + col)       = v0;
        *(float2*)(outp + (size_t)(rowA + 8) * DD + col) = v1;
    }
}

// ---- block reductions over 512 threads (16 warps) ----
__device__ __forceinline__ float blockReduceSum(float v, float* red) {
    int tid = threadIdx.x, lane = tid & 31, wid = tid >> 5;
    #pragma unroll
    for (int o = 16; o > 0; o >>= 1) v += __shfl_down_sync(0xffffffffu, v, o);
    if (lane == 0) red[wid] = v;
    __syncthreads();
    if (wid == 0) {
        float x = (lane < 16) ? red[lane] : 0.0f;
        #pragma unroll
        for (int o = 8; o > 0; o >>= 1) x += __shfl_down_sync(0xffffffffu, x, o);
        if (lane == 0) red[0] = x;
    }
    __syncthreads();
    float r = red[0];
    __syncthreads();
    return r;
}

__device__ __forceinline__ float blockReduceMax(float v, float* red) {
    int tid = threadIdx.x, lane = tid & 31, wid = tid >> 5;
    #pragma unroll
    for (int o = 16; o > 0; o >>= 1) v = fmaxf(v, __shfl_down_sync(0xffffffffu, v, o));
    if (lane == 0) red[wid] = v;
    __syncthreads();
    if (wid == 0) {
        float x = (lane < 16) ? red[lane] : -3.4e38f;
        #pragma unroll
        for (int o = 8; o > 0; o >>= 1) x = fmaxf(x, __shfl_down_sync(0xffffffffu, x, o));
        if (lane == 0) red[0] = x;
    }
    __syncthreads();
    float r = red[0];
    __syncthreads();
    return r;
}

__device__ __forceinline__ float blockReduceMin(float v, float* red) {
    int tid = threadIdx.x, lane = tid & 31, wid = tid >> 5;
    #pragma unroll
    for (int o = 16; o > 0; o >>= 1) v = fminf(v, __shfl_down_sync(0xffffffffu, v, o));
    if (lane == 0) red[wid] = v;
    __syncthreads();
    if (wid == 0) {
        float x = (lane < 16) ? red[lane] : 3.4e38f;
        #pragma unroll
        for (int o = 8; o > 0; o >>= 1) x = fminf(x, __shfl_down_sync(0xffffffffu, x, o));
        if (lane == 0) red[0] = x;
    }
    __syncthreads();
    float r = red[0];
    __syncthreads();
    return r;
}

// ---- main fused kernel: one block per (batch, channel) ----
__global__ void __launch_bounds__(512)
k_main(Ptr3 x, Ptr3 h, Ptr3 kq,
       const float* __restrict__ kn_g, const float* __restrict__ kn_b,
       const float* __restrict__ norm_g, const float* __restrict__ norm_b)
{
    extern __shared__ float E[];              // [512][TJ+1]
    __shared__ float s_s[DD], s_u2[DD], s_v[DD];
    __shared__ float Zpart[16][TJ + 1];
    __shared__ float coefT[TJ];
    __shared__ float red[32];

    const int ESTR = TJ + 1;

    int b = blockIdx.x, c = blockIdx.y, tid = threadIdx.x;
    int row = c * BB + b;

    float wk = g_wk[(size_t)row * DD + tid];
    float wq = g_wq[(size_t)row * DD + tid];
    float kv = h.p[c][(size_t)b * DD + tid];
    float qv = kq.p[c][(size_t)b * DD + tid];
    float vv = x.p[c][(size_t)b * DD + tid];

    const float inv_d = 1.0f / (float)DD;
    float mu_wk  = blockReduceSum(wk, red) * inv_d;
    float dk     = wk - mu_wk;
    float var_wk = blockReduceSum(dk * dk, red) * inv_d;
    float mu_wq  = blockReduceSum(wq, red) * inv_d;
    float dq     = wq - mu_wq;
    float var_wq = blockReduceSum(dq * dq, red) * inv_d;

    float gg = kn_g[tid];
    float cb = kn_b[tid];

    float si = kv * rsqrtf(kv * kv * var_wk + EPSF);
    float ti = qv * rsqrtf(qv * qv * var_wq + EPSF);
    float Ai = dk * gg;
    float Bi = dq * gg;

    float P    = blockReduceSum(Ai * ti, red);
    float Qs   = blockReduceSum(Ai, red);
    float smax = blockReduceMax(si, red);
    float smin = blockReduceMin(si, red);

    float u2 = (P * Bi + Qs * cb) * LOG2E_F;
    s_s[tid]  = si;
    s_u2[tid] = u2;
    s_v[tid]  = vv;
    __syncthreads();

    int g = tid >> 5;
    int j = tid & 31;

    float acc = 0.0f;

    #pragma unroll 1
    for (int jt = 0; jt < DD; jt += TJ) {
        float u2j = s_u2[jt + j];
        float m2j = fmaxf(u2j * smax, u2j * smin);
        float Zl = 0.0f;

        float* Ecol = E + (size_t)(g * 32) * ESTR + j;
        const float* sbase = s_s + g * 32;
        #pragma unroll
        for (int i4 = 0; i4 < 32; i4 += 4) {
            float4 s4 = *(const float4*)(sbase + i4);
            float e0 = ex2f(fmaf(s4.x, u2j, -m2j));
            float e1 = ex2f(fmaf(s4.y, u2j, -m2j));
            float e2 = ex2f(fmaf(s4.z, u2j, -m2j));
            float e3 = ex2f(fmaf(s4.w, u2j, -m2j));
            Zl += (e0 + e1) + (e2 + e3);
            Ecol[(i4 + 0) * ESTR] = e0;
            Ecol[(i4 + 1) * ESTR] = e1;
            Ecol[(i4 + 2) * ESTR] = e2;
            Ecol[(i4 + 3) * ESTR] = e3;
        }
        Zpart[g][j] = Zl;
        __syncthreads();

        if (tid < TJ) {
            float zt = 0.0f;
            #pragma unroll
            for (int w = 0; w < 16; w++) zt += Zpart[w][tid];
            coefT[tid] = s_v[jt + tid] / zt;
        }
        __syncthreads();

        const float* Erow = E + (size_t)tid * ESTR;
        #pragma unroll
        for (int jj = 0; jj < TJ; jj += 4) {
            float c0 = coefT[jj + 0], c1 = coefT[jj + 1];
            float c2 = coefT[jj + 2], c3 = coefT[jj + 3];
            acc = fmaf(c0, Erow[jj + 0], acc);
            acc = fmaf(c1, Erow[jj + 1], acc);
            acc = fmaf(c2, Erow[jj + 2], acc);
            acc = fmaf(c3, Erow[jj + 3], acc);
        }
        __syncthreads();
    }

    float y     = acc + vv;
    float mu_y  = blockReduceSum(y, red) * inv_d;
    float dy    = y - mu_y;
    float var_y = blockReduceSum(dy * dy, red) * inv_d;
    float yn    = dy * rsqrtf(var_y + EPSF) * norm_g[tid] + norm_b[tid];

    g_y[(size_t)row * DD + tid] = yn;
}

extern "C" void kernel_launch(void* const* d_in, const int* in_sizes, int n_in,
                              void* d_out, int out_size)
{
    (void)in_sizes; (void)n_in; (void)out_size;
    const float* r    = (const float*)d_in[0];
    const float* g    = (const float*)d_in[1];
    const float* b    = (const float*)d_in[2];
    const float* h_r  = (const float*)d_in[3];
    const float* h_g  = (const float*)d_in[4];
    const float* h_b  = (const float*)d_in[5];
    const float* k_r  = (const float*)d_in[6];
    const float* k_g  = (const float*)d_in[7];
    const float* k_b  = (const float*)d_in[8];
    const float* Wk   = (const float*)d_in[9];
    const float* bk   = (const float*)d_in[10];
    const float* Wq   = (const float*)d_in[11];
    const float* bq   = (const float*)d_in[12];
    const float* kn_g = (const float*)d_in[13];
    const float* kn_b = (const float*)d_in[14];
    const float* norm_g = (const float*)d_in[15];
    const float* norm_b = (const float*)d_in[16];
    const float* fc_w = (const float*)d_in[17];
    const float* fc_b = (const float*)d_in[18];
    float* out = (float*)d_out;

    Ptr3 X  = {{ r,   g,   b   }};
    Ptr3 H  = {{ h_r, h_g, h_b }};
    Ptr3 KQ = {{ k_r, k_g, k_b }};

    const size_t E_BYTES = (size_t)DD * (TJ + 1) * sizeof(float);

    static float* wt_dev = nullptr;
    static float* wk_dev = nullptr;
    static float* wq_dev = nullptr;
    static float* y_dev  = nullptr;
    if (wt_dev == nullptr) {
        void* p = nullptr;
        cudaGetSymbolAddress(&p, g_wt); wt_dev = (float*)p;
        cudaGetSymbolAddress(&p, g_wk); wk_dev = (float*)p;
        cudaGetSymbolAddress(&p, g_wq); wq_dev = (float*)p;
        cudaGetSymbolAddress(&p, g_y);  y_dev  = (float*)p;
        cudaFuncSetAttribute(k_main, cudaFuncAttributeMaxDynamicSharedMemorySize,
                             (int)E_BYTES);
        cudaFuncSetAttribute(k_gemm7<false>, cudaFuncAttributeMaxDynamicSharedMemorySize,
                             G7_SMEM);
        cudaFuncSetAttribute(k_gemm7<true>, cudaFuncAttributeMaxDynamicSharedMemorySize,
                             G7_SMEM);
    }

    // Stage 0: transpose weights -> g_wt (k-major)
    k_transpose<<<dim3(16, 16, 3), dim3(32, 8)>>>(Wk, Wq, fc_w);

    // Stage 1: w_k = h @ Wk.T + bk ; w_q = kidx @ Wq.T + bq
    {
        G7 a;
        a.src[0] = H;            a.src[1] = KQ;
        a.wt[0]  = wt_dev;       a.wt[1]  = wt_dev + DD * DD;
        a.bias[0] = bk;          a.bias[1] = bq;
        a.out[0] = wk_dev;       a.out[1] = wq_dev;
        k_gemm7<false><<<dim3(12, 8, 2), 128, G7_SMEM>>>(a);
    }

    // Stage 2: collapsed attention + residual + LN -> g_y
    k_main<<<dim3(BB, 3), 512, E_BYTES>>>(X, H, KQ, kn_g, kn_b, norm_g, norm_b);

    // Stage 3: out = y @ fc_w.T + fc_b + y
    {
        Ptr3 Y = {{ y_dev, y_dev + BB * DD, y_dev + 2 * BB * DD }};
        G7 a;
        a.src[0] = Y;            a.src[1] = Y;
        a.wt[0]  = wt_dev + 2 * DD * DD;  a.wt[1] = a.wt[0];
        a.bias[0] = fc_b;        a.bias[1] = fc_b;
        a.out[0] = out;          a.out[1] = out;
        k_gemm7<true><<<dim3(12, 8, 1), 128, G7_SMEM>>>(a);
    }
}

// round 8
// speedup vs baseline: 1.2443x; 1.2443x over previous
#include <cuda_runtime.h>

#define DD 512
#define BB 128
#define EPSF 1e-5f
#define LOG2E_F 1.4426950408889634f
#define TJ 32
#define MATSZ (384 * 512)

// scratch (static device memory — no allocations)
__device__ float g_y [3 * BB * DD];
__device__ float g_wt[3 * DD * DD];     // k-major weights: [mat][k][m]
__device__ float g_part[4 * MATSZ];     // K-split partials

struct Ptr3 { const float* p[3]; };

__device__ __forceinline__ float ex2f(float x) {
    float y;
    asm("ex2.approx.ftz.f32 %0, %1;" : "=f"(y) : "f"(x));
    return y;
}

// ===================== transpose weights: g_wt[z][d][m] = W_z[m][d] =====================
__global__ void __launch_bounds__(256)
k_transpose(const float* __restrict__ W0, const float* __restrict__ W1,
            const float* __restrict__ W2)
{
    __shared__ float t[32][33];
    const float* W = (blockIdx.z == 0) ? W0 : (blockIdx.z == 1) ? W1 : W2;
    float* O = g_wt + (size_t)blockIdx.z * DD * DD;
    int x  = blockIdx.x * 32 + threadIdx.x;
    int y0 = blockIdx.y * 32;
    #pragma unroll
    for (int i = threadIdx.y; i < 32; i += 8)
        t[i][threadIdx.x] = W[(size_t)(y0 + i) * DD + x];
    __syncthreads();
    int xo  = blockIdx.y * 32 + threadIdx.x;
    int yo0 = blockIdx.x * 32;
    #pragma unroll
    for (int i = threadIdx.y; i < 32; i += 8)
        O[(size_t)(yo0 + i) * DD + xo] = t[threadIdx.x][i];
}

// ===================== GEMM v8: 32r x 64c tile, K-split 2, smem-staged =====================
// g_part[z][row][col] = sum_{k in half ks} src[row][k] * wt[k][col]
// block 128 thr; thread tile 4r x 4c; K=256 in 4 chunks of 64.
// grid: (rowtiles=12, coltiles=8, z = mat*2 + ks)
struct G8 {
    Ptr3 src[2];
    const float* wt[2];     // k-major [512][512]
};

#define A8STR 68
#define W8STR 68

__global__ void __launch_bounds__(128)
k_gemm8(G8 a)
{
    __shared__ __align__(16) float sA[32][A8STR];   // 8.5 KB
    __shared__ __align__(16) float sW[64][W8STR];   // 17 KB

    int tid = threadIdx.x;
    int rt = blockIdx.x, ct = blockIdx.y, z = blockIdx.z;
    int mat = z >> 1, ks = z & 1;
    int r0 = rt * 32;
    const float* src = a.src[mat].p[r0 >> 7] + (size_t)(r0 & 127) * DD;
    const float* wt  = a.wt[mat] + ct * 64;
    int k0 = ks * 256;

    int c4 = tid & 15;     // 16 col-quads -> 64 cols
    int rq = tid >> 4;     // 8 row-quads -> 32 rows

    float acc[4][4];
    #pragma unroll
    for (int j = 0; j < 4; j++)
        #pragma unroll
        for (int i = 0; i < 4; i++) acc[j][i] = 0.0f;

    #pragma unroll 1
    for (int ch = 0; ch < 4; ch++) {
        int kb = k0 + ch * 64;
        // stage A chunk: 32 rows x 64 k (row-major, coalesced)
        #pragma unroll
        for (int it = 0; it < 4; it++) {
            int idx = it * 128 + tid;
            int row = idx >> 4, q = idx & 15;
            *(float4*)&sA[row][q * 4] =
                *(const float4*)(src + (size_t)row * DD + kb + q * 4);
        }
        // stage W chunk: 64 k x 64 c (k-major, coalesced)
        #pragma unroll
        for (int it = 0; it < 8; it++) {
            int idx = it * 128 + tid;
            int kk = idx >> 4, q = idx & 15;
            *(float4*)&sW[kk][q * 4] =
                *(const float4*)(wt + (size_t)(kb + kk) * DD + q * 4);
        }
        __syncthreads();

        #pragma unroll 4
        for (int dd = 0; dd < 64; dd++) {
            float4 w = *(const float4*)&sW[dd][c4 * 4];
            float a0 = sA[4 * rq + 0][dd];
            float a1 = sA[4 * rq + 1][dd];
            float a2 = sA[4 * rq + 2][dd];
            float a3 = sA[4 * rq + 3][dd];
            acc[0][0] = fmaf(a0, w.x, acc[0][0]);
            acc[0][1] = fmaf(a0, w.y, acc[0][1]);
            acc[0][2] = fmaf(a0, w.z, acc[0][2]);
            acc[0][3] = fmaf(a0, w.w, acc[0][3]);
            acc[1][0] = fmaf(a1, w.x, acc[1][0]);
            acc[1][1] = fmaf(a1, w.y, acc[1][1]);
            acc[1][2] = fmaf(a1, w.z, acc[1][2]);
            acc[1][3] = fmaf(a1, w.w, acc[1][3]);
            acc[2][0] = fmaf(a2, w.x, acc[2][0]);
            acc[2][1] = fmaf(a2, w.y, acc[2][1]);
            acc[2][2] = fmaf(a2, w.z, acc[2][2]);
            acc[2][3] = fmaf(a2, w.w, acc[2][3]);
            acc[3][0] = fmaf(a3, w.x, acc[3][0]);
            acc[3][1] = fmaf(a3, w.y, acc[3][1]);
            acc[3][2] = fmaf(a3, w.z, acc[3][2]);
            acc[3][3] = fmaf(a3, w.w, acc[3][3]);
        }
        __syncthreads();
    }

    float* outp = g_part + (size_t)z * MATSZ;
    #pragma unroll
    for (int j = 0; j < 4; j++) {
        float4 v = make_float4(acc[j][0], acc[j][1], acc[j][2], acc[j][3]);
        *(float4*)(outp + (size_t)(r0 + 4 * rq + j) * DD + ct * 64 + c4 * 4) = v;
    }
}

// ===================== fc final reduce: out = p0 + p1 + fc_b + y =====================
__global__ void __launch_bounds__(512)
k_reduce2(const float* __restrict__ fcb, float* __restrict__ out)
{
    int t = threadIdx.x;
    size_t i = (size_t)blockIdx.x * DD + t;
    out[i] = g_part[i] + g_part[MATSZ + i] + fcb[t] + g_y[i];
}

// ---- block reductions over 512 threads (16 warps) ----
__device__ __forceinline__ float blockReduceSum(float v, float* red) {
    int tid = threadIdx.x, lane = tid & 31, wid = tid >> 5;
    #pragma unroll
    for (int o = 16; o > 0; o >>= 1) v += __shfl_down_sync(0xffffffffu, v, o);
    if (lane == 0) red[wid] = v;
    __syncthreads();
    if (wid == 0) {
        float x = (lane < 16) ? red[lane] : 0.0f;
        #pragma unroll
        for (int o = 8; o > 0; o >>= 1) x += __shfl_down_sync(0xffffffffu, x, o);
        if (lane == 0) red[0] = x;
    }
    __syncthreads();
    float r = red[0];
    __syncthreads();
    return r;
}

__device__ __forceinline__ float blockReduceMax(float v, float* red) {
    int tid = threadIdx.x, lane = tid & 31, wid = tid >> 5;
    #pragma unroll
    for (int o = 16; o > 0; o >>= 1) v = fmaxf(v, __shfl_down_sync(0xffffffffu, v, o));
    if (lane == 0) red[wid] = v;
    __syncthreads();
    if (wid == 0) {
        float x = (lane < 16) ? red[lane] : -3.4e38f;
        #pragma unroll
        for (int o = 8; o > 0; o >>= 1) x = fmaxf(x, __shfl_down_sync(0xffffffffu, x, o));
        if (lane == 0) red[0] = x;
    }
    __syncthreads();
    float r = red[0];
    __syncthreads();
    return r;
}

__device__ __forceinline__ float blockReduceMin(float v, float* red) {
    int tid = threadIdx.x, lane = tid & 31, wid = tid >> 5;
    #pragma unroll
    for (int o = 16; o > 0; o >>= 1) v = fminf(v, __shfl_down_sync(0xffffffffu, v, o));
    if (lane == 0) red[wid] = v;
    __syncthreads();
    if (wid == 0) {
        float x = (lane < 16) ? red[lane] : 3.4e38f;
        #pragma unroll
        for (int o = 8; o > 0; o >>= 1) x = fminf(x, __shfl_down_sync(0xffffffffu, x, o));
        if (lane == 0) red[0] = x;
    }
    __syncthreads();
    float r = red[0];
    __syncthreads();
    return r;
}

// ---- main fused kernel: one block per (batch, channel) ----
// Folds the stage-1 K-split reduction + bias into its loads.
__global__ void __launch_bounds__(512)
k_main(Ptr3 x, Ptr3 h, Ptr3 kq,
       const float* __restrict__ bk, const float* __restrict__ bq,
       const float* __restrict__ kn_g, const float* __restrict__ kn_b,
       const float* __restrict__ norm_g, const float* __restrict__ norm_b)
{
    extern __shared__ float E[];              // [512][TJ+1]
    __shared__ float s_s[DD], s_u2[DD], s_v[DD];
    __shared__ float Zpart[16][TJ + 1];
    __shared__ float coefT[TJ];
    __shared__ float red[32];

    const int ESTR = TJ + 1;

    int b = blockIdx.x, c = blockIdx.y, tid = threadIdx.x;
    int row = c * BB + b;
    size_t ri = (size_t)row * DD + tid;

    float wk = g_part[ri] + g_part[MATSZ + ri] + bk[tid];
    float wq = g_part[2 * MATSZ + ri] + g_part[3 * MATSZ + ri] + bq[tid];
    float kv = h.p[c][(size_t)b * DD + tid];
    float qv = kq.p[c][(size_t)b * DD + tid];
    float vv = x.p[c][(size_t)b * DD + tid];

    const float inv_d = 1.0f / (float)DD;
    float mu_wk  = blockReduceSum(wk, red) * inv_d;
    float dk     = wk - mu_wk;
    float var_wk = blockReduceSum(dk * dk, red) * inv_d;
    float mu_wq  = blockReduceSum(wq, red) * inv_d;
    float dq     = wq - mu_wq;
    float var_wq = blockReduceSum(dq * dq, red) * inv_d;

    float gg = kn_g[tid];
    float cb = kn_b[tid];

    float si = kv * rsqrtf(kv * kv * var_wk + EPSF);
    float ti = qv * rsqrtf(qv * qv * var_wq + EPSF);
    float Ai = dk * gg;
    float Bi = dq * gg;

    float P    = blockReduceSum(Ai * ti, red);
    float Qs   = blockReduceSum(Ai, red);
    float smax = blockReduceMax(si, red);
    float smin = blockReduceMin(si, red);

    float u2 = (P * Bi + Qs * cb) * LOG2E_F;
    s_s[tid]  = si;
    s_u2[tid] = u2;
    s_v[tid]  = vv;
    __syncthreads();

    int g = tid >> 5;
    int j = tid & 31;

    float acc = 0.0f;

    #pragma unroll 1
    for (int jt = 0; jt < DD; jt += TJ) {
        float u2j = s_u2[jt + j];
        float m2j = fmaxf(u2j * smax, u2j * smin);
        float Zl = 0.0f;

        float* Ecol = E + (size_t)(g * 32) * ESTR + j;
        const float* sbase = s_s + g * 32;
        #pragma unroll
        for (int i4 = 0; i4 < 32; i4 += 4) {
            float4 s4 = *(const float4*)(sbase + i4);
            float e0 = ex2f(fmaf(s4.x, u2j, -m2j));
            float e1 = ex2f(fmaf(s4.y, u2j, -m2j));
            float e2 = ex2f(fmaf(s4.z, u2j, -m2j));
            float e3 = ex2f(fmaf(s4.w, u2j, -m2j));
            Zl += (e0 + e1) + (e2 + e3);
            Ecol[(i4 + 0) * ESTR] = e0;
            Ecol[(i4 + 1) * ESTR] = e1;
            Ecol[(i4 + 2) * ESTR] = e2;
            Ecol[(i4 + 3) * ESTR] = e3;
        }
        Zpart[g][j] = Zl;
        __syncthreads();

        if (tid < TJ) {
            float zt = 0.0f;
            #pragma unroll
            for (int w = 0; w < 16; w++) zt += Zpart[w][tid];
            coefT[tid] = s_v[jt + tid] / zt;
        }
        __syncthreads();

        const float* Erow = E + (size_t)tid * ESTR;
        #pragma unroll
        for (int jj = 0; jj < TJ; jj += 4) {
            float c0 = coefT[jj + 0], c1 = coefT[jj + 1];
            float c2 = coefT[jj + 2], c3 = coefT[jj + 3];
            acc = fmaf(c0, Erow[jj + 0], acc);
            acc = fmaf(c1, Erow[jj + 1], acc);
            acc = fmaf(c2, Erow[jj + 2], acc);
            acc = fmaf(c3, Erow[jj + 3], acc);
        }
        __syncthreads();
    }

    float y     = acc + vv;
    float mu_y  = blockReduceSum(y, red) * inv_d;
    float dy    = y - mu_y;
    float var_y = blockReduceSum(dy * dy, red) * inv_d;
    float yn    = dy * rsqrtf(var_y + EPSF) * norm_g[tid] + norm_b[tid];

    g_y[(size_t)row * DD + tid] = yn;
}

extern "C" void kernel_launch(void* const* d_in, const int* in_sizes, int n_in,
                              void* d_out, int out_size)
{
    (void)in_sizes; (void)n_in; (void)out_size;
    const float* r    = (const float*)d_in[0];
    const float* g    = (const float*)d_in[1];
    const float* b    = (const float*)d_in[2];
    const float* h_r  = (const float*)d_in[3];
    const float* h_g  = (const float*)d_in[4];
    const float* h_b  = (const float*)d_in[5];
    const float* k_r  = (const float*)d_in[6];
    const float* k_g  = (const float*)d_in[7];
    const float* k_b  = (const float*)d_in[8];
    const float* Wk   = (const float*)d_in[9];
    const float* bk   = (const float*)d_in[10];
    const float* Wq   = (const float*)d_in[11];
    const float* bq   = (const float*)d_in[12];
    const float* kn_g = (const float*)d_in[13];
    const float* kn_b = (const float*)d_in[14];
    const float* norm_g = (const float*)d_in[15];
    const float* norm_b = (const float*)d_in[16];
    const float* fc_w = (const float*)d_in[17];
    const float* fc_b = (const float*)d_in[18];
    float* out = (float*)d_out;

    Ptr3 X  = {{ r,   g,   b   }};
    Ptr3 H  = {{ h_r, h_g, h_b }};
    Ptr3 KQ = {{ k_r, k_g, k_b }};

    const size_t E_BYTES = (size_t)DD * (TJ + 1) * sizeof(float);

    static float* wt_dev = nullptr;
    static float* y_dev  = nullptr;
    if (wt_dev == nullptr) {
        void* p = nullptr;
        cudaGetSymbolAddress(&p, g_wt); wt_dev = (float*)p;
        cudaGetSymbolAddress(&p, g_y);  y_dev  = (float*)p;
        cudaFuncSetAttribute(k_main, cudaFuncAttributeMaxDynamicSharedMemorySize,
                             (int)E_BYTES);
    }

    // Stage 0: transpose weights -> g_wt (k-major)
    k_transpose<<<dim3(16, 16, 3), dim3(32, 8)>>>(Wk, Wq, fc_w);

    // Stage 1: w_k / w_q partials (K-split 2), z = mat*2 + ks
    {
        G8 a;
        a.src[0] = H;            a.src[1] = KQ;
        a.wt[0]  = wt_dev;       a.wt[1]  = wt_dev + DD * DD;
        k_gemm8<<<dim3(12, 8, 4), 128>>>(a);
    }

    // Stage 2: folds stage-1 partials + bias; attention + residual + LN -> g_y
    k_main<<<dim3(BB, 3), 512, E_BYTES>>>(X, H, KQ, bk, bq,
                                          kn_g, kn_b, norm_g, norm_b);

    // Stage 3: fc partials (K-split 2), src = g_y
    {
        Ptr3 Y = {{ y_dev, y_dev + BB * DD, y_dev + 2 * BB * DD }};
        G8 a;
        a.src[0] = Y;            a.src[1] = Y;
        a.wt[0]  = wt_dev + 2 * DD * DD;  a.wt[1] = a.wt[0];
        k_gemm8<<<dim3(12, 8, 2), 128>>>(a);
    }

    // Stage 4: out = p0 + p1 + fc_b + y
    k_reduce2<<<384, 512>>>(fc_b, out);
}

// round 9
// speedup vs baseline: 1.4210x; 1.1421x over previous
#include <cuda_runtime.h>

#define DD 512
#define BB 128
#define EPSF 1e-5f
#define LOG2E_F 1.4426950408889634f
#define TJ 32
#define MATSZ (384 * 512)

// scratch (static device memory — no allocations)
__device__ float g_y [3 * BB * DD];
__device__ float g_wt[3 * DD * DD];     // k-major weights: [mat][k][m]
__device__ float g_part[8 * MATSZ];     // K-split partials

struct Ptr3 { const float* p[3]; };

__device__ __forceinline__ float ex2f(float x) {
    float y;
    asm("ex2.approx.ftz.f32 %0, %1;" : "=f"(y) : "f"(x));
    return y;
}

// ===================== transpose weights: g_wt[z][d][m] = W_z[m][d] =====================
__global__ void __launch_bounds__(256)
k_transpose(const float* __restrict__ W0, const float* __restrict__ W1,
            const float* __restrict__ W2)
{
    __shared__ float t[32][33];
    const float* W = (blockIdx.z == 0) ? W0 : (blockIdx.z == 1) ? W1 : W2;
    float* O = g_wt + (size_t)blockIdx.z * DD * DD;
    int x  = blockIdx.x * 32 + threadIdx.x;
    int y0 = blockIdx.y * 32;
    #pragma unroll
    for (int i = threadIdx.y; i < 32; i += 8)
        t[i][threadIdx.x] = W[(size_t)(y0 + i) * DD + x];
    __syncthreads();
    int xo  = blockIdx.y * 32 + threadIdx.x;
    int yo0 = blockIdx.x * 32;
    #pragma unroll
    for (int i = threadIdx.y; i < 32; i += 8)
        O[(size_t)(yo0 + i) * DD + xo] = t[threadIdx.x][i];
}

// ===================== GEMM v9: 32r x 64c tile, K-split 4, smem-staged =====================
// g_part[z][row][col] = sum_{k in quarter ks} src[row][k] * wt[k][col]
// block 128 thr; thread tile 4r x 4c; K=128 in 2 chunks of 64.
// grid: (rowtiles=12, coltiles=8, z = mat*4 + ks)
struct G9 {
    Ptr3 src[2];
    const float* wt[2];     // k-major [512][512]
};

#define A8STR 68
#define W8STR 68

__global__ void __launch_bounds__(128)
k_gemm9(G9 a)
{
    __shared__ __align__(16) float sA[32][A8STR];   // 8.5 KB
    __shared__ __align__(16) float sW[64][W8STR];   // 17 KB

    int tid = threadIdx.x;
    int rt = blockIdx.x, ct = blockIdx.y, z = blockIdx.z;
    int mat = z >> 2, ks = z & 3;
    int r0 = rt * 32;
    const float* src = a.src[mat].p[r0 >> 7] + (size_t)(r0 & 127) * DD;
    const float* wt  = a.wt[mat] + ct * 64;
    int k0 = ks * 128;

    int c4 = tid & 15;     // 16 col-quads -> 64 cols
    int rq = tid >> 4;     // 8 row-quads -> 32 rows

    float acc[4][4];
    #pragma unroll
    for (int j = 0; j < 4; j++)
        #pragma unroll
        for (int i = 0; i < 4; i++) acc[j][i] = 0.0f;

    #pragma unroll 1
    for (int ch = 0; ch < 2; ch++) {
        int kb = k0 + ch * 64;
        // stage A chunk: 32 rows x 64 k (row-major, coalesced)
        #pragma unroll
        for (int it = 0; it < 4; it++) {
            int idx = it * 128 + tid;
            int row = idx >> 4, q = idx & 15;
            *(float4*)&sA[row][q * 4] =
                *(const float4*)(src + (size_t)row * DD + kb + q * 4);
        }
        // stage W chunk: 64 k x 64 c (k-major, coalesced)
        #pragma unroll
        for (int it = 0; it < 8; it++) {
            int idx = it * 128 + tid;
            int kk = idx >> 4, q = idx & 15;
            *(float4*)&sW[kk][q * 4] =
                *(const float4*)(wt + (size_t)(kb + kk) * DD + q * 4);
        }
        __syncthreads();

        #pragma unroll 4
        for (int dd = 0; dd < 64; dd++) {
            float4 w = *(const float4*)&sW[dd][c4 * 4];
            float a0 = sA[4 * rq + 0][dd];
            float a1 = sA[4 * rq + 1][dd];
            float a2 = sA[4 * rq + 2][dd];
            float a3 = sA[4 * rq + 3][dd];
            acc[0][0] = fmaf(a0, w.x, acc[0][0]);
            acc[0][1] = fmaf(a0, w.y, acc[0][1]);
            acc[0][2] = fmaf(a0, w.z, acc[0][2]);
            acc[0][3] = fmaf(a0, w.w, acc[0][3]);
            acc[1][0] = fmaf(a1, w.x, acc[1][0]);
            acc[1][1] = fmaf(a1, w.y, acc[1][1]);
            acc[1][2] = fmaf(a1, w.z, acc[1][2]);
            acc[1][3] = fmaf(a1, w.w, acc[1][3]);
            acc[2][0] = fmaf(a2, w.x, acc[2][0]);
            acc[2][1] = fmaf(a2, w.y, acc[2][1]);
            acc[2][2] = fmaf(a2, w.z, acc[2][2]);
            acc[2][3] = fmaf(a2, w.w, acc[2][3]);
            acc[3][0] = fmaf(a3, w.x, acc[3][0]);
            acc[3][1] = fmaf(a3, w.y, acc[3][1]);
            acc[3][2] = fmaf(a3, w.z, acc[3][2]);
            acc[3][3] = fmaf(a3, w.w, acc[3][3]);
        }
        __syncthreads();
    }

    float* outp = g_part + (size_t)z * MATSZ;
    #pragma unroll
    for (int j = 0; j < 4; j++) {
        float4 v = make_float4(acc[j][0], acc[j][1], acc[j][2], acc[j][3]);
        *(float4*)(outp + (size_t)(r0 + 4 * rq + j) * DD + ct * 64 + c4 * 4) = v;
    }
}

// ===================== fc final reduce: out = p0..p3 + fc_b + y =====================
__global__ void __launch_bounds__(512)
k_reduce2(const float* __restrict__ fcb, float* __restrict__ out)
{
    int t = threadIdx.x;
    size_t i = (size_t)blockIdx.x * DD + t;
    out[i] = ((g_part[i] + g_part[MATSZ + i])
            + (g_part[2 * MATSZ + i] + g_part[3 * MATSZ + i]))
            + fcb[t] + g_y[i];
}

// ---- block reductions over 512 threads (16 warps) ----
__device__ __forceinline__ float blockReduceSum(float v, float* red) {
    int tid = threadIdx.x, lane = tid & 31, wid = tid >> 5;
    #pragma unroll
    for (int o = 16; o > 0; o >>= 1) v += __shfl_down_sync(0xffffffffu, v, o);
    if (lane == 0) red[wid] = v;
    __syncthreads();
    if (wid == 0) {
        float x = (lane < 16) ? red[lane] : 0.0f;
        #pragma unroll
        for (int o = 8; o > 0; o >>= 1) x += __shfl_down_sync(0xffffffffu, x, o);
        if (lane == 0) red[0] = x;
    }
    __syncthreads();
    float r = red[0];
    __syncthreads();
    return r;
}

__device__ __forceinline__ float blockReduceMax(float v, float* red) {
    int tid = threadIdx.x, lane = tid & 31, wid = tid >> 5;
    #pragma unroll
    for (int o = 16; o > 0; o >>= 1) v = fmaxf(v, __shfl_down_sync(0xffffffffu, v, o));
    if (lane == 0) red[wid] = v;
    __syncthreads();
    if (wid == 0) {
        float x = (lane < 16) ? red[lane] : -3.4e38f;
        #pragma unroll
        for (int o = 8; o > 0; o >>= 1) x = fmaxf(x, __shfl_down_sync(0xffffffffu, x, o));
        if (lane == 0) red[0] = x;
    }
    __syncthreads();
    float r = red[0];
    __syncthreads();
    return r;
}

__device__ __forceinline__ float blockReduceMin(float v, float* red) {
    int tid = threadIdx.x, lane = tid & 31, wid = tid >> 5;
    #pragma unroll
    for (int o = 16; o > 0; o >>= 1) v = fminf(v, __shfl_down_sync(0xffffffffu, v, o));
    if (lane == 0) red[wid] = v;
    __syncthreads();
    if (wid == 0) {
        float x = (lane < 16) ? red[lane] : 3.4e38f;
        #pragma unroll
        for (int o = 8; o > 0; o >>= 1) x = fminf(x, __shfl_down_sync(0xffffffffu, x, o));
        if (lane == 0) red[0] = x;
    }
    __syncthreads();
    float r = red[0];
    __syncthreads();
    return r;
}

// ---- main fused kernel: one block per (batch, channel) ----
// Folds the stage-1 K-split-4 reduction + bias into its loads.
__global__ void __launch_bounds__(512)
k_main(Ptr3 x, Ptr3 h, Ptr3 kq,
       const float* __restrict__ bk, const float* __restrict__ bq,
       const float* __restrict__ kn_g, const float* __restrict__ kn_b,
       const float* __restrict__ norm_g, const float* __restrict__ norm_b)
{
    extern __shared__ float E[];              // [512][TJ+1]
    __shared__ float s_s[DD], s_u2[DD], s_v[DD];
    __shared__ float Zpart[16][TJ + 1];
    __shared__ float coefT[TJ];
    __shared__ float red[32];

    const int ESTR = TJ + 1;

    int b = blockIdx.x, c = blockIdx.y, tid = threadIdx.x;
    int row = c * BB + b;
    size_t ri = (size_t)row * DD + tid;

    float wk = ((g_part[ri] + g_part[MATSZ + ri])
              + (g_part[2 * MATSZ + ri] + g_part[3 * MATSZ + ri])) + bk[tid];
    float wq = ((g_part[4 * MATSZ + ri] + g_part[5 * MATSZ + ri])
              + (g_part[6 * MATSZ + ri] + g_part[7 * MATSZ + ri])) + bq[tid];
    float kv = h.p[c][(size_t)b * DD + tid];
    float qv = kq.p[c][(size_t)b * DD + tid];
    float vv = x.p[c][(size_t)b * DD + tid];

    const float inv_d = 1.0f / (float)DD;
    float mu_wk  = blockReduceSum(wk, red) * inv_d;
    float dk     = wk - mu_wk;
    float var_wk = blockReduceSum(dk * dk, red) * inv_d;
    float mu_wq  = blockReduceSum(wq, red) * inv_d;
    float dq     = wq - mu_wq;
    float var_wq = blockReduceSum(dq * dq, red) * inv_d;

    float gg = kn_g[tid];
    float cb = kn_b[tid];

    float si = kv * rsqrtf(kv * kv * var_wk + EPSF);
    float ti = qv * rsqrtf(qv * qv * var_wq + EPSF);
    float Ai = dk * gg;
    float Bi = dq * gg;

    float P    = blockReduceSum(Ai * ti, red);
    float Qs   = blockReduceSum(Ai, red);
    float smax = blockReduceMax(si, red);
    float smin = blockReduceMin(si, red);

    float u2 = (P * Bi + Qs * cb) * LOG2E_F;
    s_s[tid]  = si;
    s_u2[tid] = u2;
    s_v[tid]  = vv;
    __syncthreads();

    int g = tid >> 5;
    int j = tid & 31;

    float acc = 0.0f;

    #pragma unroll 1
    for (int jt = 0; jt < DD; jt += TJ) {
        float u2j = s_u2[jt + j];
        float m2j = fmaxf(u2j * smax, u2j * smin);
        float Zl = 0.0f;

        float* Ecol = E + (size_t)(g * 32) * ESTR + j;
        const float* sbase = s_s + g * 32;
        #pragma unroll
        for (int i4 = 0; i4 < 32; i4 += 4) {
            float4 s4 = *(const float4*)(sbase + i4);
            float e0 = ex2f(fmaf(s4.x, u2j, -m2j));
            float e1 = ex2f(fmaf(s4.y, u2j, -m2j));
            float e2 = ex2f(fmaf(s4.z, u2j, -m2j));
            float e3 = ex2f(fmaf(s4.w, u2j, -m2j));
            Zl += (e0 + e1) + (e2 + e3);
            Ecol[(i4 + 0) * ESTR] = e0;
            Ecol[(i4 + 1) * ESTR] = e1;
            Ecol[(i4 + 2) * ESTR] = e2;
            Ecol[(i4 + 3) * ESTR] = e3;
        }
        Zpart[g][j] = Zl;
        __syncthreads();

        if (tid < TJ) {
            float zt = 0.0f;
            #pragma unroll
            for (int w = 0; w < 16; w++) zt += Zpart[w][tid];
            coefT[tid] = s_v[jt + tid] / zt;
        }
        __syncthreads();

        const float* Erow = E + (size_t)tid * ESTR;
        #pragma unroll
        for (int jj = 0; jj < TJ; jj += 4) {
            float c0 = coefT[jj + 0], c1 = coefT[jj + 1];
            float c2 = coefT[jj + 2], c3 = coefT[jj + 3];
            acc = fmaf(c0, Erow[jj + 0], acc);
            acc = fmaf(c1, Erow[jj + 1], acc);
            acc = fmaf(c2, Erow[jj + 2], acc);
            acc = fmaf(c3, Erow[jj + 3], acc);
        }
        __syncthreads();
    }

    float y     = acc + vv;
    float mu_y  = blockReduceSum(y, red) * inv_d;
    float dy    = y - mu_y;
    float var_y = blockReduceSum(dy * dy, red) * inv_d;
    float yn    = dy * rsqrtf(var_y + EPSF) * norm_g[tid] + norm_b[tid];

    g_y[(size_t)row * DD + tid] = yn;
}

extern "C" void kernel_launch(void* const* d_in, const int* in_sizes, int n_in,
                              void* d_out, int out_size)
{
    (void)in_sizes; (void)n_in; (void)out_size;
    const float* r    = (const float*)d_in[0];
    const float* g    = (const float*)d_in[1];
    const float* b    = (const float*)d_in[2];
    const float* h_r  = (const float*)d_in[3];
    const float* h_g  = (const float*)d_in[4];
    const float* h_b  = (const float*)d_in[5];
    const float* k_r  = (const float*)d_in[6];
    const float* k_g  = (const float*)d_in[7];
    const float* k_b  = (const float*)d_in[8];
    const float* Wk   = (const float*)d_in[9];
    const float* bk   = (const float*)d_in[10];
    const float* Wq   = (const float*)d_in[11];
    const float* bq   = (const float*)d_in[12];
    const float* kn_g = (const float*)d_in[13];
    const float* kn_b = (const float*)d_in[14];
    const float* norm_g = (const float*)d_in[15];
    const float* norm_b = (const float*)d_in[16];
    const float* fc_w = (const float*)d_in[17];
    const float* fc_b = (const float*)d_in[18];
    float* out = (float*)d_out;

    Ptr3 X  = {{ r,   g,   b   }};
    Ptr3 H  = {{ h_r, h_g, h_b }};
    Ptr3 KQ = {{ k_r, k_g, k_b }};

    const size_t E_BYTES = (size_t)DD * (TJ + 1) * sizeof(float);

    static float* wt_dev = nullptr;
    static float* y_dev  = nullptr;
    if (wt_dev == nullptr) {
        void* p = nullptr;
        cudaGetSymbolAddress(&p, g_wt); wt_dev = (float*)p;
        cudaGetSymbolAddress(&p, g_y);  y_dev  = (float*)p;
        cudaFuncSetAttribute(k_main, cudaFuncAttributeMaxDynamicSharedMemorySize,
                             (int)E_BYTES);
    }

    // Stage 0: transpose weights -> g_wt (k-major)
    k_transpose<<<dim3(16, 16, 3), dim3(32, 8)>>>(Wk, Wq, fc_w);

    // Stage 1: w_k / w_q partials (K-split 4), z = mat*4 + ks
    {
        G9 a;
        a.src[0] = H;            a.src[1] = KQ;
        a.wt[0]  = wt_dev;       a.wt[1]  = wt_dev + DD * DD;
        k_gemm9<<<dim3(12, 8, 8), 128>>>(a);
    }

    // Stage 2: folds stage-1 partials + bias; attention + residual + LN -> g_y
    k_main<<<dim3(BB, 3), 512, E_BYTES>>>(X, H, KQ, bk, bq,
                                          kn_g, kn_b, norm_g, norm_b);

    // Stage 3: fc partials (K-split 4), src = g_y, mat fixed 0
    {
        Ptr3 Y = {{ y_dev, y_dev + BB * DD, y_dev + 2 * BB * DD }};
        G9 a;
        a.src[0] = Y;            a.src[1] = Y;
        a.wt[0]  = wt_dev + 2 * DD * DD;  a.wt[1] = a.wt[0];
        k_gemm9<<<dim3(12, 8, 4), 128>>>(a);
    }

    // Stage 4: out = p0+p1+p2+p3 + fc_b + y
    k_reduce2<<<384, 512>>>(fc_b, out);
}